// round 7
// baseline (speedup 1.0000x reference)
#include <cuda_runtime.h>
#include <cstdint>

// LocalAttention fused kernel v3 (sm_103a).
// T[b,l,j] = dot(x[b,l,:], W[j,:]) for 18 rows (aw3:0-2, aw5:3-7, aw7:8-14, cw:15-17)
// out_k[b,l] = tanh( sigmoid(shifted-sum of T + ab_k) * T[.,dcol_k] + cb_k )
//
// v3 vs v2 (74us):
//  - j-dimension split across 2 thread groups -> 18 packed accs/thread (36 regs)
//  - 256-thread blocks, launch_bounds(256,4): 32 warps/SM (was 16)
//  - quad-buffered cp.async, ONE __syncthreads per chunk (was 2)
//  - grid = 512 blocks = exactly one wave at 4 blocks/SM

typedef unsigned long long ull;

#define FMA2(d, a, b) \
    asm("fma.rn.f32x2 %0, %1, %2, %0;" : "+l"(d) : "l"(a), "l"(b))

__device__ __forceinline__ float unpk_sum(ull v) {
    float lo, hi;
    asm("mov.b64 {%0, %1}, %2;" : "=f"(lo), "=f"(hi) : "l"(v));
    return lo + hi;
}

__device__ __forceinline__ float sigm(float v) {
    return 1.0f / (1.0f + __expf(-v));
}

constexpr int Lc = 500;
constexpr int Ec = 300;
constexpr int E4 = 75;            // float4 per x row
constexpr int POS = 256;          // positions per block (250 outputs + 6 halo)
constexpr int TL  = 250;
constexpr int NJ  = 18;
constexpr int JG  = 9;            // j-rows per thread group
constexpr int CH  = 2;            // float4 per chunk per row
constexpr int NCHUNK = 38;        // ceil(75/2), last chunk zero-padded
constexpr int WPITCH = 304;       // floats per weight row (300 + 4 zero pad)
constexpr int XROW_W = 8;         // words per row per chunk buffer
constexpr int XBUF_W = POS * XROW_W;               // 2048 words = 8KB
constexpr int NBUF = 4;
constexpr int WS_OFF = NBUF * XBUF_W;              // 8192 words
constexpr int SMEM_WORDS = WS_OFF + NJ * WPITCH;   // 13664
constexpr int SMEM_BYTES = SMEM_WORDS * 4;         // 54656 B

__global__ __launch_bounds__(256, 4)
void la_fused3(const float* __restrict__ x,
               const float* __restrict__ aw3, const float* __restrict__ ab3,
               const float* __restrict__ cw3, const float* __restrict__ cb3,
               const float* __restrict__ aw5, const float* __restrict__ ab5,
               const float* __restrict__ cw5, const float* __restrict__ cb5,
               const float* __restrict__ aw7, const float* __restrict__ ab7,
               const float* __restrict__ cw7, const float* __restrict__ cb7,
               float* __restrict__ out, int Ltot)
{
    extern __shared__ float sm[];
    float* ws = sm + WS_OFF;

    const int tid  = threadIdx.x;
    const int b    = blockIdx.y;
    const int tile = blockIdx.x;
    const int l_base = tile * TL - 3;
    const float* xrow0 = x + (size_t)b * Lc * Ec;

    // ---- weights -> shared (covered by first in-loop barrier) ----
    for (int i = tid; i < 3 * Ec; i += 256) ws[(     i / Ec) * WPITCH + (i % Ec)] = aw3[i];
    for (int i = tid; i < 5 * Ec; i += 256) ws[(3 +  i / Ec) * WPITCH + (i % Ec)] = aw5[i];
    for (int i = tid; i < 7 * Ec; i += 256) ws[(8 +  i / Ec) * WPITCH + (i % Ec)] = aw7[i];
    for (int i = tid; i < Ec; i += 256) {
        ws[15 * WPITCH + i] = cw3[i];
        ws[16 * WPITCH + i] = cw5[i];
        ws[17 * WPITCH + i] = cw7[i];
    }
    if (tid < NJ * 4) ws[(tid >> 2) * WPITCH + 300 + (tid & 3)] = 0.0f;  // pad col

    uint32_t sbase;
    asm("{ .reg .u64 t; cvta.to.shared.u64 t, %1; cvt.u32.u64 %0, t; }"
        : "=r"(sbase) : "l"(sm));

    // stage chunk c (2 float4 per row, 256 rows) into buffer c%4; empty commit
    // past the end keeps the wait_group count consistent.
    auto stage = [&](int c) {
        if (c < NCHUNK) {
            const uint32_t base = sbase + (uint32_t)(c & 3) * XBUF_W * 4;
            #pragma unroll
            for (int i = 0; i < 2; ++i) {
                int f = tid + i * 256;            // 0..511 = 256 rows x 2 e
                int r = f >> 1;
                int e = f & 1;
                int l  = l_base + r;
                int eg = c * CH + e;
                bool v = (l >= 0) && (l < Lc) && (eg < E4);
                const float* g = xrow0 + (v ? ((size_t)l * Ec + eg * 4) : 0);
                uint32_t s = base + (uint32_t)(r * XROW_W + ((e ^ ((r >> 2) & 1)) << 2)) * 4;
                int sz = v ? 16 : 0;
                asm volatile("cp.async.cg.shared.global [%0], [%1], 16, %2;"
                             :: "r"(s), "l"(g), "r"(sz));
            }
        }
        asm volatile("cp.async.commit_group;");
    };

    // thread t: group g = t>>7 handles j in [g*9, g*9+9), positions u and u+128
    const int u = tid & 127;
    const int jbase = (tid >> 7) * JG;
    const int posA = u, posB = u + 128;
    const int sw = ((u >> 2) & 1) << 2;     // same for posA and posB (+128 rows)

    ull accA[JG], accB[JG];
    #pragma unroll
    for (int j = 0; j < JG; ++j) { accA[j] = 0ull; accB[j] = 0ull; }

    stage(0);
    stage(1);

    for (int c = 0; c < NCHUNK; ++c) {
        stage(c + 2);
        asm volatile("cp.async.wait_group 2;" ::: "memory");
        __syncthreads();

        const float* xb = sm + (c & 3) * XBUF_W;
        const float* pA = xb + posA * XROW_W;
        const float* pB = xb + posB * XROW_W;
        const float* wc = ws + jbase * WPITCH + c * (CH * 4);

        #pragma unroll
        for (int e = 0; e < CH; ++e) {
            const int sl = (e << 2) ^ sw;
            ulonglong2 xa = *(const ulonglong2*)(pA + sl);
            ulonglong2 xv = *(const ulonglong2*)(pB + sl);
            #pragma unroll
            for (int j = 0; j < JG; ++j) {
                ulonglong2 wv = *(const ulonglong2*)(wc + j * WPITCH + e * 4);
                FMA2(accA[j], xa.x, wv.x);
                FMA2(accA[j], xa.y, wv.y);
                FMA2(accB[j], xv.x, wv.x);
                FMA2(accB[j], xv.y, wv.y);
            }
        }
    }
    __syncthreads();   // weights + x buffers dead below; Tsh aliases them

    // ---- T buffer aliased over x buffers (+ head of ws): 256*19 words ----
    float* Tsh = sm;
    #pragma unroll
    for (int j = 0; j < JG; ++j) {
        Tsh[posA * 19 + jbase + j] = unpk_sum(accA[j]);
        Tsh[posB * 19 + jbase + j] = unpk_sum(accB[j]);
    }
    __syncthreads();

    // ---- epilogue: shifted sums + sigmoid gate + tanh ----
    const int pos = tid;
    if (pos >= 3 && pos <= 252) {
        const float* T0 = &Tsh[pos * 19];
        float s3 = Tsh[(pos - 1) * 19 + 0] + T0[1] + Tsh[(pos + 1) * 19 + 2];
        float s5 = 0.f;
        #pragma unroll
        for (int j = 0; j < 5; ++j) s5 += Tsh[(pos - 2 + j) * 19 + 3 + j];
        float s7 = 0.f;
        #pragma unroll
        for (int j = 0; j < 7; ++j) s7 += Tsh[(pos - 3 + j) * 19 + 8 + j];

        float o3 = tanhf(sigm(s3 + ab3[0]) * T0[15] + cb3[0]);
        float o5 = tanhf(sigm(s5 + ab5[0]) * T0[16] + cb5[0]);
        float o7 = tanhf(sigm(s7 + ab7[0]) * T0[17] + cb7[0]);

        const int l_out = l_base + pos;
        const size_t oi = (size_t)b * Lc + l_out;
        out[oi]                    = o3;
        out[(size_t)Ltot + oi]     = o5;
        out[2 * (size_t)Ltot + oi] = o7;
    }
}

extern "C" void kernel_launch(void* const* d_in, const int* in_sizes, int n_in,
                              void* d_out, int out_size) {
    const float* x   = (const float*)d_in[0];
    const float* aw3 = (const float*)d_in[1];
    const float* ab3 = (const float*)d_in[2];
    const float* cw3 = (const float*)d_in[3];
    const float* cb3 = (const float*)d_in[4];
    const float* aw5 = (const float*)d_in[5];
    const float* ab5 = (const float*)d_in[6];
    const float* cw5 = (const float*)d_in[7];
    const float* cb5 = (const float*)d_in[8];
    const float* aw7 = (const float*)d_in[9];
    const float* ab7 = (const float*)d_in[10];
    const float* cw7 = (const float*)d_in[11];
    const float* cb7 = (const float*)d_in[12];
    float* out = (float*)d_out;

    const int Bn   = in_sizes[0] / (Lc * Ec);   // 256
    const int Ltot = Bn * Lc;

    cudaFuncSetAttribute(la_fused3, cudaFuncAttributeMaxDynamicSharedMemorySize,
                         SMEM_BYTES);

    dim3 grid(2, Bn);
    dim3 block(256);
    la_fused3<<<grid, block, SMEM_BYTES>>>(x,
                                           aw3, ab3, cw3, cb3,
                                           aw5, ab5, cw5, cb5,
                                           aw7, ab7, cw7, cb7,
                                           out, Ltot);
}